// round 3
// baseline (speedup 1.0000x reference)
#include <cuda_runtime.h>

// MultiCellLSTM: B=4096, T=512, H=64, gates 4H=256.
// R3: 8 rows/warp, 128 threads/CTA, 128 CTAs (1 warp per SMSP).
// Weight LDS.128 (conflict-free swizzle) now amortized over 8 rows ->
// crossbar ~3.2K cyc/step/SM, below the FFMA2 floor (~4.3K).
// h pre-duplicated in warp-private smem; sync-free loop (__syncwarp only).

typedef unsigned long long u64;

#define NTHR   128
#define NCTA   128
#define WS_U64 (3 * 64 * 128)   // 24576 u64 : recurrent weights
#define CMB_U64 (3 * 4 * 128)   // 1536  u64 : bias + input-weight cols
#define HD_U64 (32 * 64)        // 2048  u64 : duplicated h, 32 rows x 64 units
#define SMEM_BYTES ((WS_U64 + CMB_U64 + HD_U64) * 8)  // 225280

__device__ __forceinline__ float ex2f(float x) { float y; asm("ex2.approx.f32 %0, %1;" : "=f"(y) : "f"(x)); return y; }
__device__ __forceinline__ float rcpf(float x) { float y; asm("rcp.approx.f32 %0, %1;" : "=f"(y) : "f"(x)); return y; }
__device__ __forceinline__ float sigf(float x) { return rcpf(1.0f + ex2f(-1.4426950408889634f * x)); }
__device__ __forceinline__ float tnhf(float x) { return fmaf(2.0f, rcpf(1.0f + ex2f(-2.8853900817779268f * x)), -1.0f); }

__device__ __forceinline__ u64 pk2(float a, float b) { u64 r; asm("mov.b64 %0, {%1, %2};" : "=l"(r) : "f"(a), "f"(b)); return r; }
__device__ __forceinline__ void up2(u64 v, float& a, float& b) { asm("mov.b64 {%0, %1}, %2;" : "=f"(a), "=f"(b) : "l"(v)); }
__device__ __forceinline__ u64 ffma2(u64 a, u64 b, u64 c) { u64 d; asm("fma.rn.f32x2 %0, %1, %2, %3;" : "=l"(d) : "l"(a), "l"(b), "l"(c)); return d; }

// One LSTM step for cell type TY (0: x1+x2+x3, 1: x1+x2, 2: x1 only).
// Lane owns units {2l,2l+1} x 8 rows. Weight k-row layout (1024B):
//   16B slot = l*32 + ((h ^ (l>>2))&1)*16; h=0 -> classes(i,f), h=1 -> (g,o).
// Half-swap makes each 8-lane LDS.128 phase tile all 32 banks once.
template<int TY>
__device__ __forceinline__ void do_step(
    const char* __restrict__ wsB, const char* __restrict__ cmB,
    char* __restrict__ hb,                  // this warp's dup'd-h base (8 rows x 512B)
    int offA, int offB, int lane,
    const float (&xv1)[8], const float (&xv2)[8], const float (&xv3)[8],
    float (&cst)[8][2], float (&hl)[8][2])
{
    const char* wcell = wsB + TY * 65536;   // 64 k-rows * 1024B
    const char* cc    = cmB + TY * 4096;    // 4 arrays * 1024B

    u64 acc[4][8];  // [class i,f,g,o][row]

    {   // bias (bih+bhh prefolded)
        ulonglong2 bA = *(const ulonglong2*)(cc + offA);
        ulonglong2 bB = *(const ulonglong2*)(cc + offB);
        #pragma unroll
        for (int r = 0; r < 8; r++) { acc[0][r] = bA.x; acc[1][r] = bA.y; acc[2][r] = bB.x; acc[3][r] = bB.y; }
    }
    {   // + Wi[:,0] * x1
        ulonglong2 wA = *(const ulonglong2*)(cc + 1024 + offA);
        ulonglong2 wB = *(const ulonglong2*)(cc + 1024 + offB);
        #pragma unroll
        for (int r = 0; r < 8; r++) {
            u64 xd = pk2(xv1[r], xv1[r]);
            acc[0][r] = ffma2(wA.x, xd, acc[0][r]); acc[1][r] = ffma2(wA.y, xd, acc[1][r]);
            acc[2][r] = ffma2(wB.x, xd, acc[2][r]); acc[3][r] = ffma2(wB.y, xd, acc[3][r]);
        }
    }
    if (TY <= 1) {  // + Wi[:,1] * x2
        ulonglong2 wA = *(const ulonglong2*)(cc + 2048 + offA);
        ulonglong2 wB = *(const ulonglong2*)(cc + 2048 + offB);
        #pragma unroll
        for (int r = 0; r < 8; r++) {
            u64 xd = pk2(xv2[r], xv2[r]);
            acc[0][r] = ffma2(wA.x, xd, acc[0][r]); acc[1][r] = ffma2(wA.y, xd, acc[1][r]);
            acc[2][r] = ffma2(wB.x, xd, acc[2][r]); acc[3][r] = ffma2(wB.y, xd, acc[3][r]);
        }
    }
    if (TY == 0) {  // + Wi[:,2] * x3
        ulonglong2 wA = *(const ulonglong2*)(cc + 3072 + offA);
        ulonglong2 wB = *(const ulonglong2*)(cc + 3072 + offB);
        #pragma unroll
        for (int r = 0; r < 8; r++) {
            u64 xd = pk2(xv3[r], xv3[r]);
            acc[0][r] = ffma2(wA.x, xd, acc[0][r]); acc[1][r] = ffma2(wA.y, xd, acc[1][r]);
            acc[2][r] = ffma2(wB.x, xd, acc[2][r]); acc[3][r] = ffma2(wB.y, xd, acc[3][r]);
        }
    }

    // recurrent: acc += Wh[:,k] * h[k]; k in pairs, weights shared by 8 rows
    #pragma unroll 4
    for (int m = 0; m < 32; m++) {
        const char* base = wcell + m * 2048;
        ulonglong2 w0A = *(const ulonglong2*)(base + offA);
        ulonglong2 w0B = *(const ulonglong2*)(base + offB);
        ulonglong2 w1A = *(const ulonglong2*)(base + 1024 + offA);
        ulonglong2 w1B = *(const ulonglong2*)(base + 1024 + offB);
        #pragma unroll
        for (int r = 0; r < 8; r++) {
            ulonglong2 hd = *(const ulonglong2*)(hb + r * 512 + m * 16);  // (dup h_2m, dup h_2m+1)
            acc[0][r] = ffma2(w0A.x, hd.x, acc[0][r]);
            acc[1][r] = ffma2(w0A.y, hd.x, acc[1][r]);
            acc[2][r] = ffma2(w0B.x, hd.x, acc[2][r]);
            acc[3][r] = ffma2(w0B.y, hd.x, acc[3][r]);
            acc[0][r] = ffma2(w1A.x, hd.y, acc[0][r]);
            acc[1][r] = ffma2(w1A.y, hd.y, acc[1][r]);
            acc[2][r] = ffma2(w1B.x, hd.y, acc[2][r]);
            acc[3][r] = ffma2(w1B.y, hd.y, acc[3][r]);
        }
    }

    __syncwarp();  // all lanes done READING h(t)
    #pragma unroll
    for (int r = 0; r < 8; r++) {
        float gi0, gi1, gf0, gf1, gg0, gg1, go0, go1;
        up2(acc[0][r], gi0, gi1);
        up2(acc[1][r], gf0, gf1);
        up2(acc[2][r], gg0, gg1);
        up2(acc[3][r], go0, go1);
        float c0 = fmaf(sigf(gf0), cst[r][0], sigf(gi0) * tnhf(gg0));
        float c1 = fmaf(sigf(gf1), cst[r][1], sigf(gi1) * tnhf(gg1));
        cst[r][0] = c0; cst[r][1] = c1;
        float h0 = sigf(go0) * tnhf(c0);
        float h1 = sigf(go1) * tnhf(c1);
        hl[r][0] = h0; hl[r][1] = h1;
        ulonglong2 st; st.x = pk2(h0, h0); st.y = pk2(h1, h1);
        *(ulonglong2*)(hb + r * 512 + lane * 16) = st;   // dup'd store
    }
    __syncwarp();  // h(t+1) visible to all lanes
}

__global__ __launch_bounds__(NTHR, 1) void mclstm_kernel(
    const float* __restrict__ x1, const float* __restrict__ x2, const float* __restrict__ x3,
    const float* __restrict__ Wih3, const float* __restrict__ Whh3,
    const float* __restrict__ bih3, const float* __restrict__ bhh3,
    const float* __restrict__ Wih2, const float* __restrict__ Whh2,
    const float* __restrict__ bih2, const float* __restrict__ bhh2,
    const float* __restrict__ Wih1, const float* __restrict__ Whh1,
    const float* __restrict__ bih1, const float* __restrict__ bhh1,
    const float* __restrict__ Wout, const float* __restrict__ bOut,
    float* __restrict__ out)
{
    extern __shared__ u64 sm[];
    u64* ws   = sm;
    u64* cmb  = ws + WS_U64;
    u64* hdup = cmb + CMB_U64;

    const int tid = threadIdx.x;

    // ---- stage recurrent weights: ws[(ty*64+k)*128 + slot] ----
    for (int idx = tid; idx < WS_U64; idx += NTHR) {
        int ty = idx >> 13, rem = idx & 8191, k = rem >> 7, s = rem & 127;
        int l = s >> 2, swz = (s >> 1) & 1, col = s & 1;
        int h = swz ^ ((l >> 2) & 1);
        int q = 2 * h + col;
        const float* W = (ty == 0) ? Whh3 : (ty == 1) ? Whh2 : Whh1;
        int g0 = (q * 64 + 2 * l) * 64 + k;
        ws[idx] = pk2(W[g0], W[g0 + 64]);
    }
    // ---- stage bias + input-weight cols: cmb[(ty*4+arr)*128 + slot] ----
    for (int idx = tid; idx < CMB_U64; idx += NTHR) {
        int ty = idx >> 9, rem = idx & 511, arr = rem >> 7, s = rem & 127;
        int l = s >> 2, swz = (s >> 1) & 1, col = s & 1;
        int h = swz ^ ((l >> 2) & 1);
        int q = 2 * h + col;
        int j0 = q * 64 + 2 * l, j1 = j0 + 1;
        const float *bi, *bh, *wi; int wic;
        if (ty == 0)      { bi = bih3; bh = bhh3; wi = Wih3; wic = 3; }
        else if (ty == 1) { bi = bih2; bh = bhh2; wi = Wih2; wic = 2; }
        else              { bi = bih1; bh = bhh1; wi = Wih1; wic = 1; }
        float a, b;
        if (arr == 0) { a = bi[j0] + bh[j0]; b = bi[j1] + bh[j1]; }
        else {
            int cx = arr - 1;
            if (cx < wic) { a = wi[j0 * wic + cx]; b = wi[j1 * wic + cx]; }
            else          { a = 0.f; b = 0.f; }
        }
        cmb[idx] = pk2(a, b);
    }
    for (int idx = tid; idx < HD_U64; idx += NTHR) hdup[idx] = 0ull;
    __syncthreads();

    const int lane = tid & 31, w = tid >> 5;
    const int row0 = blockIdx.x * 32 + w * 8;

    const int s0   = ((lane >> 2) & 1) * 16;
    const int offA = lane * 32 + s0;        // classes (i,f)
    const int offB = lane * 32 + 16 - s0;   // classes (g,o)

    const char* wsB = (const char*)ws;
    const char* cmB = (const char*)cmb;
    char* hb = (char*)(hdup + (size_t)w * 8 * 64);   // warp-private, 4KB

    float cst[8][2], hl[8][2];
    #pragma unroll
    for (int r = 0; r < 8; r++) { cst[r][0] = cst[r][1] = 0.f; hl[r][0] = hl[r][1] = 0.f; }

    const float* x1r = x1 + (size_t)row0 * 512;
    const float* x2r = x2 + (size_t)row0 * 256;
    const float* x3r = x3 + (size_t)row0 * 128;

    for (int b = 0; b < 128; b++) {
        float a1[8][4], a2[8][2], a3[8];
        #pragma unroll
        for (int r = 0; r < 8; r++) {
            float4 v = *(const float4*)(x1r + (size_t)r * 512 + b * 4);
            a1[r][0] = v.x; a1[r][1] = v.y; a1[r][2] = v.z; a1[r][3] = v.w;
            float2 u = *(const float2*)(x2r + (size_t)r * 256 + b * 2);
            a2[r][0] = u.x; a2[r][1] = u.y;
            a3[r] = x3r[(size_t)r * 128 + b];
        }
        float t1[8], t2[8];
        #pragma unroll
        for (int r = 0; r < 8; r++) { t1[r] = a1[r][0]; t2[r] = a2[r][0]; }
        do_step<0>(wsB, cmB, hb, offA, offB, lane, t1, t2, a3, cst, hl);   // t%4==0

        #pragma unroll
        for (int r = 0; r < 8; r++) t1[r] = a1[r][1];
        do_step<2>(wsB, cmB, hb, offA, offB, lane, t1, t1, t1, cst, hl);   // t%4==1

        #pragma unroll
        for (int r = 0; r < 8; r++) { t1[r] = a1[r][2]; t2[r] = a2[r][1]; }
        do_step<1>(wsB, cmB, hb, offA, offB, lane, t1, t2, t2, cst, hl);   // t%4==2

        #pragma unroll
        for (int r = 0; r < 8; r++) t1[r] = a1[r][3];
        do_step<2>(wsB, cmB, hb, offA, offB, lane, t1, t1, t1, cst, hl);   // t%4==3
    }

    // out[row] = sigmoid(h . Wout + bOut): lane holds 2 units per row
    const float wo0 = Wout[2 * lane], wo1 = Wout[2 * lane + 1];
    const float bo = bOut[0];
    #pragma unroll
    for (int r = 0; r < 8; r++) {
        float pw = hl[r][0] * wo0 + hl[r][1] * wo1;
        pw += __shfl_xor_sync(0xffffffffu, pw, 16);
        pw += __shfl_xor_sync(0xffffffffu, pw, 8);
        pw += __shfl_xor_sync(0xffffffffu, pw, 4);
        pw += __shfl_xor_sync(0xffffffffu, pw, 2);
        pw += __shfl_xor_sync(0xffffffffu, pw, 1);
        if (lane == 0) out[row0 + r] = sigf(pw + bo);
    }
}

extern "C" void kernel_launch(void* const* d_in, const int* in_sizes, int n_in,
                              void* d_out, int out_size) {
    const float* x1   = (const float*)d_in[0];
    const float* x2   = (const float*)d_in[1];
    const float* x3   = (const float*)d_in[2];
    const float* Wih3 = (const float*)d_in[3];
    const float* Whh3 = (const float*)d_in[4];
    const float* bih3 = (const float*)d_in[5];
    const float* bhh3 = (const float*)d_in[6];
    const float* Wih2 = (const float*)d_in[7];
    const float* Whh2 = (const float*)d_in[8];
    const float* bih2 = (const float*)d_in[9];
    const float* bhh2 = (const float*)d_in[10];
    const float* Wih1 = (const float*)d_in[11];
    const float* Whh1 = (const float*)d_in[12];
    const float* bih1 = (const float*)d_in[13];
    const float* bhh1 = (const float*)d_in[14];
    const float* Wout = (const float*)d_in[15];
    const float* bOut = (const float*)d_in[16];

    cudaFuncSetAttribute(mclstm_kernel, cudaFuncAttributeMaxDynamicSharedMemorySize, SMEM_BYTES);

    mclstm_kernel<<<NCTA, NTHR, SMEM_BYTES>>>(
        x1, x2, x3,
        Wih3, Whh3, bih3, bhh3,
        Wih2, Whh2, bih2, bhh2,
        Wih1, Whh1, bih1, bhh1,
        Wout, bOut, (float*)d_out);
}

// round 4
// speedup vs baseline: 1.4624x; 1.4624x over previous
#include <cuda_runtime.h>

// MultiCellLSTM: B=4096, T=512, H=64, gates 4H=256.
// R4: back to R2 shape (256 thr, 4 rows/warp, 128 CTAs, 2 warps/SMSP) +
//  - bias/input-weights held in registers (no cmb smem traffic)
//  - h double-buffered -> single __syncwarp per step
//  - tanh.approx.f32 activations (sigmoid = 0.5*tanh(x/2)+0.5)
//  - deeper unroll on the k-loop

typedef unsigned long long u64;

#define NTHR   256
#define NCTA   128
#define WS_U64 (3 * 64 * 128)       // 24576 u64 : recurrent weights (192KB)
#define HD_U64 (2 * 32 * 64)        // 4096  u64 : double-buffered dup'd h (32KB)
#define SMEM_BYTES ((WS_U64 + HD_U64) * 8)   // 229376

__device__ __forceinline__ float ex2f(float x) { float y; asm("ex2.approx.f32 %0, %1;" : "=f"(y) : "f"(x)); return y; }
__device__ __forceinline__ float rcpf(float x) { float y; asm("rcp.approx.f32 %0, %1;" : "=f"(y) : "f"(x)); return y; }
__device__ __forceinline__ float sigp(float x) { return rcpf(1.0f + ex2f(-1.4426950408889634f * x)); }  // precise-ish (final out)
__device__ __forceinline__ float tha(float x) { float y; asm("tanh.approx.f32 %0, %1;" : "=f"(y) : "f"(x)); return y; }
__device__ __forceinline__ float sga(float x) { return fmaf(0.5f, tha(0.5f * x), 0.5f); }

__device__ __forceinline__ u64 pk2(float a, float b) { u64 r; asm("mov.b64 %0, {%1, %2};" : "=l"(r) : "f"(a), "f"(b)); return r; }
__device__ __forceinline__ void up2(u64 v, float& a, float& b) { asm("mov.b64 {%0, %1}, %2;" : "=f"(a), "=f"(b) : "l"(v)); }
__device__ __forceinline__ u64 ffma2(u64 a, u64 b, u64 c) { u64 d; asm("fma.rn.f32x2 %0, %1, %2, %3;" : "=l"(d) : "l"(a), "l"(b), "l"(c)); return d; }

// Per-lane register-resident bias + input-weight columns.
// A = classes (i,f) for units (2l, 2l+1); B = classes (g,o).
struct Cmb3 { ulonglong2 bA, bB, w1A, w1B, w2A, w2B, w3A, w3B; };
struct Cmb2 { ulonglong2 bA, bB, w1A, w1B, w2A, w2B; };
struct Cmb1 { ulonglong2 bA, bB, w1A, w1B; };

// One LSTM step for cell type TY (0: x1+x2+x3, 1: x1+x2, 2: x1 only).
// Lane owns units {2l,2l+1} x 4 rows. Weight k-row layout (1024B):
//   16B slot = l*32 + ((h ^ (l>>2))&1)*16; h=0 -> classes(i,f), h=1 -> (g,o).
// Half-swap makes each 8-lane LDS.128 phase tile all 32 banks once.
template<int TY, typename CMB>
__device__ __forceinline__ void do_step(
    const char* __restrict__ wsB, const CMB& cm,
    const char* __restrict__ hrd,   // read buffer (this warp's 4 rows x 512B)
    char* __restrict__ hwr,         // write buffer
    int lane, int offA, int offB,
    const float (&xv1)[4], const float (&xv2)[4], const float (&xv3)[4],
    float (&cst)[4][2], float (&hl)[4][2])
{
    const char* wcell = wsB + TY * 65536;   // 64 k-rows * 1024B

    u64 acc[4][4];  // [class i,f,g,o][row]

    #pragma unroll
    for (int r = 0; r < 4; r++) {
        u64 xd = pk2(xv1[r], xv1[r]);
        acc[0][r] = ffma2(cm.w1A.x, xd, cm.bA.x);
        acc[1][r] = ffma2(cm.w1A.y, xd, cm.bA.y);
        acc[2][r] = ffma2(cm.w1B.x, xd, cm.bB.x);
        acc[3][r] = ffma2(cm.w1B.y, xd, cm.bB.y);
    }
    if constexpr (TY <= 1) {
        #pragma unroll
        for (int r = 0; r < 4; r++) {
            u64 xd = pk2(xv2[r], xv2[r]);
            acc[0][r] = ffma2(cm.w2A.x, xd, acc[0][r]);
            acc[1][r] = ffma2(cm.w2A.y, xd, acc[1][r]);
            acc[2][r] = ffma2(cm.w2B.x, xd, acc[2][r]);
            acc[3][r] = ffma2(cm.w2B.y, xd, acc[3][r]);
        }
    }
    if constexpr (TY == 0) {
        #pragma unroll
        for (int r = 0; r < 4; r++) {
            u64 xd = pk2(xv3[r], xv3[r]);
            acc[0][r] = ffma2(cm.w3A.x, xd, acc[0][r]);
            acc[1][r] = ffma2(cm.w3A.y, xd, acc[1][r]);
            acc[2][r] = ffma2(cm.w3B.x, xd, acc[2][r]);
            acc[3][r] = ffma2(cm.w3B.y, xd, acc[3][r]);
        }
    }

    // recurrent: acc += Wh[:,k] * h[k]; k in pairs, weights shared by 4 rows
    #pragma unroll 8
    for (int m = 0; m < 32; m++) {
        const char* base = wcell + m * 2048;
        ulonglong2 w0A = *(const ulonglong2*)(base + offA);
        ulonglong2 w0B = *(const ulonglong2*)(base + offB);
        ulonglong2 w1A = *(const ulonglong2*)(base + 1024 + offA);
        ulonglong2 w1B = *(const ulonglong2*)(base + 1024 + offB);
        #pragma unroll
        for (int r = 0; r < 4; r++) {
            ulonglong2 hd = *(const ulonglong2*)(hrd + r * 512 + m * 16);  // (dup h_2m, dup h_2m+1)
            acc[0][r] = ffma2(w0A.x, hd.x, acc[0][r]);
            acc[1][r] = ffma2(w0A.y, hd.x, acc[1][r]);
            acc[2][r] = ffma2(w0B.x, hd.x, acc[2][r]);
            acc[3][r] = ffma2(w0B.y, hd.x, acc[3][r]);
            acc[0][r] = ffma2(w1A.x, hd.y, acc[0][r]);
            acc[1][r] = ffma2(w1A.y, hd.y, acc[1][r]);
            acc[2][r] = ffma2(w1B.x, hd.y, acc[2][r]);
            acc[3][r] = ffma2(w1B.y, hd.y, acc[3][r]);
        }
    }

    // elementwise LSTM cell (writes go to the other h buffer -> no sync here)
    #pragma unroll
    for (int r = 0; r < 4; r++) {
        float gi0, gi1, gf0, gf1, gg0, gg1, go0, go1;
        up2(acc[0][r], gi0, gi1);
        up2(acc[1][r], gf0, gf1);
        up2(acc[2][r], gg0, gg1);
        up2(acc[3][r], go0, go1);
        float c0 = fmaf(sga(gf0), cst[r][0], sga(gi0) * tha(gg0));
        float c1 = fmaf(sga(gf1), cst[r][1], sga(gi1) * tha(gg1));
        cst[r][0] = c0; cst[r][1] = c1;
        float h0 = sga(go0) * tha(c0);
        float h1 = sga(go1) * tha(c1);
        hl[r][0] = h0; hl[r][1] = h1;
        ulonglong2 st; st.x = pk2(h0, h0); st.y = pk2(h1, h1);
        *(ulonglong2*)(hwr + r * 512 + lane * 16) = st;   // dup'd store
    }
}

__global__ __launch_bounds__(NTHR, 1) void mclstm_kernel(
    const float* __restrict__ x1, const float* __restrict__ x2, const float* __restrict__ x3,
    const float* __restrict__ Wih3, const float* __restrict__ Whh3,
    const float* __restrict__ bih3, const float* __restrict__ bhh3,
    const float* __restrict__ Wih2, const float* __restrict__ Whh2,
    const float* __restrict__ bih2, const float* __restrict__ bhh2,
    const float* __restrict__ Wih1, const float* __restrict__ Whh1,
    const float* __restrict__ bih1, const float* __restrict__ bhh1,
    const float* __restrict__ Wout, const float* __restrict__ bOut,
    float* __restrict__ out)
{
    extern __shared__ u64 sm[];
    u64* ws   = sm;
    u64* hdup = ws + WS_U64;   // [par][32 rows][64 u64]

    const int tid = threadIdx.x;

    // ---- stage recurrent weights: ws[(ty*64+k)*128 + slot] ----
    for (int idx = tid; idx < WS_U64; idx += NTHR) {
        int ty = idx >> 13, rem = idx & 8191, k = rem >> 7, s = rem & 127;
        int l = s >> 2, swz = (s >> 1) & 1, col = s & 1;
        int h = swz ^ ((l >> 2) & 1);
        int q = 2 * h + col;
        const float* W = (ty == 0) ? Whh3 : (ty == 1) ? Whh2 : Whh1;
        int g0 = (q * 64 + 2 * l) * 64 + k;
        ws[idx] = pk2(W[g0], W[g0 + 64]);
    }
    for (int idx = tid; idx < HD_U64; idx += NTHR) hdup[idx] = 0ull;

    const int lane = tid & 31, w = tid >> 5;
    const int row0 = blockIdx.x * 32 + w * 4;
    const int u0 = 2 * lane, u1 = u0 + 1;

    // ---- per-lane register cmb: bias(+bhh) and input-weight columns ----
    Cmb3 cm3; Cmb2 cm2; Cmb1 cm1;
    {
        // gate row = class*64 + unit; classes i=0,f=1,g=2,o=3
        #define LB(bi, bh, q) pk2(bi[(q)*64 + u0] + bh[(q)*64 + u0], bi[(q)*64 + u1] + bh[(q)*64 + u1])
        #define LW(wi, q, wic, cx) pk2(wi[((q)*64 + u0)*(wic) + (cx)], wi[((q)*64 + u1)*(wic) + (cx)])
        cm3.bA.x = LB(bih3, bhh3, 0); cm3.bA.y = LB(bih3, bhh3, 1);
        cm3.bB.x = LB(bih3, bhh3, 2); cm3.bB.y = LB(bih3, bhh3, 3);
        cm3.w1A.x = LW(Wih3, 0, 3, 0); cm3.w1A.y = LW(Wih3, 1, 3, 0);
        cm3.w1B.x = LW(Wih3, 2, 3, 0); cm3.w1B.y = LW(Wih3, 3, 3, 0);
        cm3.w2A.x = LW(Wih3, 0, 3, 1); cm3.w2A.y = LW(Wih3, 1, 3, 1);
        cm3.w2B.x = LW(Wih3, 2, 3, 1); cm3.w2B.y = LW(Wih3, 3, 3, 1);
        cm3.w3A.x = LW(Wih3, 0, 3, 2); cm3.w3A.y = LW(Wih3, 1, 3, 2);
        cm3.w3B.x = LW(Wih3, 2, 3, 2); cm3.w3B.y = LW(Wih3, 3, 3, 2);

        cm2.bA.x = LB(bih2, bhh2, 0); cm2.bA.y = LB(bih2, bhh2, 1);
        cm2.bB.x = LB(bih2, bhh2, 2); cm2.bB.y = LB(bih2, bhh2, 3);
        cm2.w1A.x = LW(Wih2, 0, 2, 0); cm2.w1A.y = LW(Wih2, 1, 2, 0);
        cm2.w1B.x = LW(Wih2, 2, 2, 0); cm2.w1B.y = LW(Wih2, 3, 2, 0);
        cm2.w2A.x = LW(Wih2, 0, 2, 1); cm2.w2A.y = LW(Wih2, 1, 2, 1);
        cm2.w2B.x = LW(Wih2, 2, 2, 1); cm2.w2B.y = LW(Wih2, 3, 2, 1);

        cm1.bA.x = LB(bih1, bhh1, 0); cm1.bA.y = LB(bih1, bhh1, 1);
        cm1.bB.x = LB(bih1, bhh1, 2); cm1.bB.y = LB(bih1, bhh1, 3);
        cm1.w1A.x = LW(Wih1, 0, 1, 0); cm1.w1A.y = LW(Wih1, 1, 1, 0);
        cm1.w1B.x = LW(Wih1, 2, 1, 0); cm1.w1B.y = LW(Wih1, 3, 1, 0);
        #undef LB
        #undef LW
    }
    __syncthreads();

    const int s0   = ((lane >> 2) & 1) * 16;
    const int offA = lane * 32 + s0;        // classes (i,f)
    const int offB = lane * 32 + 16 - s0;   // classes (g,o)

    const char* wsB = (const char*)ws;
    char* hb0 = (char*)(hdup) + (size_t)w * 4 * 512;            // par 0, warp-private 2KB
    char* hb1 = hb0 + 32 * 512;                                 // par 1

    float cst[4][2], hl[4][2];
    #pragma unroll
    for (int r = 0; r < 4; r++) { cst[r][0] = cst[r][1] = 0.f; hl[r][0] = hl[r][1] = 0.f; }

    const float* x1r = x1 + (size_t)row0 * 512;
    const float* x2r = x2 + (size_t)row0 * 256;
    const float* x3r = x3 + (size_t)row0 * 128;

    for (int b = 0; b < 128; b++) {
        float a1[4][4], a2[4][2], a3[4];
        #pragma unroll
        for (int r = 0; r < 4; r++) {
            float4 v = *(const float4*)(x1r + (size_t)r * 512 + b * 4);
            a1[r][0] = v.x; a1[r][1] = v.y; a1[r][2] = v.z; a1[r][3] = v.w;
            float2 u = *(const float2*)(x2r + (size_t)r * 256 + b * 2);
            a2[r][0] = u.x; a2[r][1] = u.y;
            a3[r] = x3r[(size_t)r * 128 + b];
        }
        float t1[4], t2[4];

        #pragma unroll
        for (int r = 0; r < 4; r++) { t1[r] = a1[r][0]; t2[r] = a2[r][0]; }
        __syncwarp();
        do_step<0>(wsB, cm3, hb0, hb1, lane, offA, offB, t1, t2, a3, cst, hl);  // t%4==0

        #pragma unroll
        for (int r = 0; r < 4; r++) t1[r] = a1[r][1];
        __syncwarp();
        do_step<2>(wsB, cm1, hb1, hb0, lane, offA, offB, t1, t1, t1, cst, hl);  // t%4==1

        #pragma unroll
        for (int r = 0; r < 4; r++) { t1[r] = a1[r][2]; t2[r] = a2[r][1]; }
        __syncwarp();
        do_step<1>(wsB, cm2, hb0, hb1, lane, offA, offB, t1, t2, t2, cst, hl);  // t%4==2

        #pragma unroll
        for (int r = 0; r < 4; r++) t1[r] = a1[r][3];
        __syncwarp();
        do_step<2>(wsB, cm1, hb1, hb0, lane, offA, offB, t1, t1, t1, cst, hl);  // t%4==3
    }

    // out[row] = sigmoid(h . Wout + bOut): lane holds 2 units per row
    const float wo0 = Wout[u0], wo1 = Wout[u1];
    const float bo = bOut[0];
    #pragma unroll
    for (int r = 0; r < 4; r++) {
        float pw = hl[r][0] * wo0 + hl[r][1] * wo1;
        pw += __shfl_xor_sync(0xffffffffu, pw, 16);
        pw += __shfl_xor_sync(0xffffffffu, pw, 8);
        pw += __shfl_xor_sync(0xffffffffu, pw, 4);
        pw += __shfl_xor_sync(0xffffffffu, pw, 2);
        pw += __shfl_xor_sync(0xffffffffu, pw, 1);
        if (lane == 0) out[row0 + r] = sigp(pw + bo);
    }
}

extern "C" void kernel_launch(void* const* d_in, const int* in_sizes, int n_in,
                              void* d_out, int out_size) {
    const float* x1   = (const float*)d_in[0];
    const float* x2   = (const float*)d_in[1];
    const float* x3   = (const float*)d_in[2];
    const float* Wih3 = (const float*)d_in[3];
    const float* Whh3 = (const float*)d_in[4];
    const float* bih3 = (const float*)d_in[5];
    const float* bhh3 = (const float*)d_in[6];
    const float* Wih2 = (const float*)d_in[7];
    const float* Whh2 = (const float*)d_in[8];
    const float* bih2 = (const float*)d_in[9];
    const float* bhh2 = (const float*)d_in[10];
    const float* Wih1 = (const float*)d_in[11];
    const float* Whh1 = (const float*)d_in[12];
    const float* bih1 = (const float*)d_in[13];
    const float* bhh1 = (const float*)d_in[14];
    const float* Wout = (const float*)d_in[15];
    const float* bOut = (const float*)d_in[16];

    cudaFuncSetAttribute(mclstm_kernel, cudaFuncAttributeMaxDynamicSharedMemorySize, SMEM_BYTES);

    mclstm_kernel<<<NCTA, NTHR, SMEM_BYTES>>>(
        x1, x2, x3,
        Wih3, Whh3, bih3, bhh3,
        Wih2, Whh2, bih2, bhh2,
        Wih1, Whh1, bih1, bhh1,
        Wout, bOut, (float*)d_out);
}

// round 8
// speedup vs baseline: 1.5166x; 1.0371x over previous
#include <cuda_runtime.h>

// MultiCellLSTM: B=4096, T=512, H=64, gates 4H=256.
// R8: R4 architecture (4 rows/warp, warp-private recurrence, smem weights
// with conflict-free swizzle, dup'd double-buffered h, register-resident
// bias/input weights, tanh.approx activations) reshaped to 7 warps x 147
// CTAs so all 148 SMs carry work (was 128/148). Main loop is warp-private
// (no CTA sync), so the CTA shape is free; surplus warps exit after init.

typedef unsigned long long u64;

#define NTHR   224                  // 7 warps
#define NCTA   147                  // 147*7 = 1029 warps >= 1024 needed
#define NWARP  7
#define WS_U64 (3 * 64 * 128)       // 24576 u64 : recurrent weights (192KB)
#define HD_U64 (2 * 28 * 64)        // 3584  u64 : double-buffered dup'd h (28KB)
#define SMEM_BYTES ((WS_U64 + HD_U64) * 8)   // 225280

__device__ __forceinline__ float ex2f(float x) { float y; asm("ex2.approx.f32 %0, %1;" : "=f"(y) : "f"(x)); return y; }
__device__ __forceinline__ float rcpf(float x) { float y; asm("rcp.approx.f32 %0, %1;" : "=f"(y) : "f"(x)); return y; }
__device__ __forceinline__ float sigp(float x) { return rcpf(1.0f + ex2f(-1.4426950408889634f * x)); }  // final out only
__device__ __forceinline__ float tha(float x) { float y; asm("tanh.approx.f32 %0, %1;" : "=f"(y) : "f"(x)); return y; }
__device__ __forceinline__ float sga(float x) { return fmaf(0.5f, tha(0.5f * x), 0.5f); }

__device__ __forceinline__ u64 pk2(float a, float b) { u64 r; asm("mov.b64 %0, {%1, %2};" : "=l"(r) : "f"(a), "f"(b)); return r; }
__device__ __forceinline__ void up2(u64 v, float& a, float& b) { asm("mov.b64 {%0, %1}, %2;" : "=f"(a), "=f"(b) : "l"(v)); }
__device__ __forceinline__ u64 ffma2(u64 a, u64 b, u64 c) { u64 d; asm("fma.rn.f32x2 %0, %1, %2, %3;" : "=l"(d) : "l"(a), "l"(b), "l"(c)); return d; }

// Per-lane register-resident bias + input-weight columns.
// A = classes (i,f) for units (2l,2l+1); B = classes (g,o).
struct Cmb3 { ulonglong2 bA, bB, w1A, w1B, w2A, w2B, w3A, w3B; };
struct Cmb2 { ulonglong2 bA, bB, w1A, w1B, w2A, w2B; };
struct Cmb1 { ulonglong2 bA, bB, w1A, w1B; };

// One LSTM step for cell type TY (0: x1+x2+x3, 1: x1+x2, 2: x1 only).
// Lane owns units {2l,2l+1} x 4 rows. Weight k-row layout (1024B):
//   16B slot = l*32 + ((h ^ (l>>2))&1)*16; h=0 -> classes(i,f), h=1 -> (g,o).
// Half-swap makes each 8-lane LDS.128 phase tile all 32 banks once.
template<int TY, typename CMB>
__device__ __forceinline__ void do_step(
    const char* __restrict__ wsB, const CMB& cm,
    const char* __restrict__ hrd,   // read buffer (this warp's 4 rows x 512B)
    char* __restrict__ hwr,         // write buffer
    int lane, int offA, int offB,
    const float (&xv1)[4], const float (&xv2)[4], const float (&xv3)[4],
    float (&cst)[4][2], float (&hl)[4][2])
{
    const char* wcell = wsB + TY * 65536;   // 64 k-rows * 1024B

    u64 acc[4][4];  // [class i,f,g,o][row]

    #pragma unroll
    for (int r = 0; r < 4; r++) {
        u64 xd = pk2(xv1[r], xv1[r]);
        acc[0][r] = ffma2(cm.w1A.x, xd, cm.bA.x);
        acc[1][r] = ffma2(cm.w1A.y, xd, cm.bA.y);
        acc[2][r] = ffma2(cm.w1B.x, xd, cm.bB.x);
        acc[3][r] = ffma2(cm.w1B.y, xd, cm.bB.y);
    }
    if constexpr (TY <= 1) {
        #pragma unroll
        for (int r = 0; r < 4; r++) {
            u64 xd = pk2(xv2[r], xv2[r]);
            acc[0][r] = ffma2(cm.w2A.x, xd, acc[0][r]);
            acc[1][r] = ffma2(cm.w2A.y, xd, acc[1][r]);
            acc[2][r] = ffma2(cm.w2B.x, xd, acc[2][r]);
            acc[3][r] = ffma2(cm.w2B.y, xd, acc[3][r]);
        }
    }
    if constexpr (TY == 0) {
        #pragma unroll
        for (int r = 0; r < 4; r++) {
            u64 xd = pk2(xv3[r], xv3[r]);
            acc[0][r] = ffma2(cm.w3A.x, xd, acc[0][r]);
            acc[1][r] = ffma2(cm.w3A.y, xd, acc[1][r]);
            acc[2][r] = ffma2(cm.w3B.x, xd, acc[2][r]);
            acc[3][r] = ffma2(cm.w3B.y, xd, acc[3][r]);
        }
    }

    // recurrent: acc += Wh[:,k] * h[k]; k in pairs, weights shared by 4 rows
    #pragma unroll 8
    for (int m = 0; m < 32; m++) {
        const char* base = wcell + m * 2048;
        ulonglong2 w0A = *(const ulonglong2*)(base + offA);
        ulonglong2 w0B = *(const ulonglong2*)(base + offB);
        ulonglong2 w1A = *(const ulonglong2*)(base + 1024 + offA);
        ulonglong2 w1B = *(const ulonglong2*)(base + 1024 + offB);
        #pragma unroll
        for (int r = 0; r < 4; r++) {
            ulonglong2 hd = *(const ulonglong2*)(hrd + r * 512 + m * 16);  // (dup h_2m, dup h_2m+1)
            acc[0][r] = ffma2(w0A.x, hd.x, acc[0][r]);
            acc[1][r] = ffma2(w0A.y, hd.x, acc[1][r]);
            acc[2][r] = ffma2(w0B.x, hd.x, acc[2][r]);
            acc[3][r] = ffma2(w0B.y, hd.x, acc[3][r]);
            acc[0][r] = ffma2(w1A.x, hd.y, acc[0][r]);
            acc[1][r] = ffma2(w1A.y, hd.y, acc[1][r]);
            acc[2][r] = ffma2(w1B.x, hd.y, acc[2][r]);
            acc[3][r] = ffma2(w1B.y, hd.y, acc[3][r]);
        }
    }

    // elementwise LSTM cell (writes go to the other h buffer -> no sync here)
    #pragma unroll
    for (int r = 0; r < 4; r++) {
        float gi0, gi1, gf0, gf1, gg0, gg1, go0, go1;
        up2(acc[0][r], gi0, gi1);
        up2(acc[1][r], gf0, gf1);
        up2(acc[2][r], gg0, gg1);
        up2(acc[3][r], go0, go1);
        float c0 = fmaf(sga(gf0), cst[r][0], sga(gi0) * tha(gg0));
        float c1 = fmaf(sga(gf1), cst[r][1], sga(gi1) * tha(gg1));
        cst[r][0] = c0; cst[r][1] = c1;
        float h0 = sga(go0) * tha(c0);
        float h1 = sga(go1) * tha(c1);
        hl[r][0] = h0; hl[r][1] = h1;
        ulonglong2 st; st.x = pk2(h0, h0); st.y = pk2(h1, h1);
        *(ulonglong2*)(hwr + r * 512 + lane * 16) = st;   // dup'd store
    }
}

__global__ __launch_bounds__(NTHR, 1) void mclstm_kernel(
    const float* __restrict__ x1, const float* __restrict__ x2, const float* __restrict__ x3,
    const float* __restrict__ Wih3, const float* __restrict__ Whh3,
    const float* __restrict__ bih3, const float* __restrict__ bhh3,
    const float* __restrict__ Wih2, const float* __restrict__ Whh2,
    const float* __restrict__ bih2, const float* __restrict__ bhh2,
    const float* __restrict__ Wih1, const float* __restrict__ Whh1,
    const float* __restrict__ bih1, const float* __restrict__ bhh1,
    const float* __restrict__ Wout, const float* __restrict__ bOut,
    float* __restrict__ out)
{
    extern __shared__ u64 sm[];
    u64* ws   = sm;
    u64* hdup = ws + WS_U64;   // [par][28 rows][64 u64]

    const int tid = threadIdx.x;

    // ---- stage recurrent weights: ws[(ty*64+k)*128 + slot] ----
    // slot s -> lane l=s>>2, 16B half swz=(s>>1)&1, col=s&1;
    // logical half h = swz ^ ((l>>2)&1); class q = 2h+col; units (2l,2l+1).
    for (int idx = tid; idx < WS_U64; idx += NTHR) {
        int ty = idx >> 13, rem = idx & 8191, k = rem >> 7, s = rem & 127;
        int l = s >> 2, swz = (s >> 1) & 1, col = s & 1;
        int h = swz ^ ((l >> 2) & 1);
        int q = 2 * h + col;
        const float* W = (ty == 0) ? Whh3 : (ty == 1) ? Whh2 : Whh1;
        int g0 = (q * 64 + 2 * l) * 64 + k;
        ws[idx] = pk2(W[g0], W[g0 + 64]);
    }
    for (int idx = tid; idx < HD_U64; idx += NTHR) hdup[idx] = 0ull;

    const int lane = tid & 31, w = tid >> 5;
    const int gw   = blockIdx.x * NWARP + w;     // global warp id
    const int row0 = gw * 4;
    const int u0 = 2 * lane, u1 = u0 + 1;

    // ---- per-lane register cmb: bias(+bhh) and input-weight columns ----
    Cmb3 cm3; Cmb2 cm2; Cmb1 cm1;
    {
        // gate row = class*64 + unit; classes i=0,f=1,g=2,o=3
        #define LB(bi, bh, q) pk2(bi[(q)*64 + u0] + bh[(q)*64 + u0], bi[(q)*64 + u1] + bh[(q)*64 + u1])
        #define LW(wi, q, wic, cx) pk2(wi[((q)*64 + u0)*(wic) + (cx)], wi[((q)*64 + u1)*(wic) + (cx)])
        cm3.bA.x = LB(bih3, bhh3, 0); cm3.bA.y = LB(bih3, bhh3, 1);
        cm3.bB.x = LB(bih3, bhh3, 2); cm3.bB.y = LB(bih3, bhh3, 3);
        cm3.w1A.x = LW(Wih3, 0, 3, 0); cm3.w1A.y = LW(Wih3, 1, 3, 0);
        cm3.w1B.x = LW(Wih3, 2, 3, 0); cm3.w1B.y = LW(Wih3, 3, 3, 0);
        cm3.w2A.x = LW(Wih3, 0, 3, 1); cm3.w2A.y = LW(Wih3, 1, 3, 1);
        cm3.w2B.x = LW(Wih3, 2, 3, 1); cm3.w2B.y = LW(Wih3, 3, 3, 1);
        cm3.w3A.x = LW(Wih3, 0, 3, 2); cm3.w3A.y = LW(Wih3, 1, 3, 2);
        cm3.w3B.x = LW(Wih3, 2, 3, 2); cm3.w3B.y = LW(Wih3, 3, 3, 2);

        cm2.bA.x = LB(bih2, bhh2, 0); cm2.bA.y = LB(bih2, bhh2, 1);
        cm2.bB.x = LB(bih2, bhh2, 2); cm2.bB.y = LB(bih2, bhh2, 3);
        cm2.w1A.x = LW(Wih2, 0, 2, 0); cm2.w1A.y = LW(Wih2, 1, 2, 0);
        cm2.w1B.x = LW(Wih2, 2, 2, 0); cm2.w1B.y = LW(Wih2, 3, 2, 0);
        cm2.w2A.x = LW(Wih2, 0, 2, 1); cm2.w2A.y = LW(Wih2, 1, 2, 1);
        cm2.w2B.x = LW(Wih2, 2, 2, 1); cm2.w2B.y = LW(Wih2, 3, 2, 1);

        cm1.bA.x = LB(bih1, bhh1, 0); cm1.bA.y = LB(bih1, bhh1, 1);
        cm1.bB.x = LB(bih1, bhh1, 2); cm1.bB.y = LB(bih1, bhh1, 3);
        cm1.w1A.x = LW(Wih1, 0, 1, 0); cm1.w1A.y = LW(Wih1, 1, 1, 0);
        cm1.w1B.x = LW(Wih1, 2, 1, 0); cm1.w1B.y = LW(Wih1, 3, 1, 0);
        #undef LB
        #undef LW
    }
    __syncthreads();

    if (row0 >= 4096) return;   // surplus warps (tail CTA) exit after init

    const int s0   = ((lane >> 2) & 1) * 16;
    const int offA = lane * 32 + s0;        // classes (i,f)
    const int offB = lane * 32 + 16 - s0;   // classes (g,o)

    const char* wsB = (const char*)ws;
    char* hb0 = (char*)hdup + (size_t)w * 4 * 512;   // par 0, warp-private 2KB
    char* hb1 = hb0 + 28 * 512;                      // par 1

    float cst[4][2], hl[4][2];
    #pragma unroll
    for (int r = 0; r < 4; r++) { cst[r][0] = cst[r][1] = 0.f; hl[r][0] = hl[r][1] = 0.f; }

    const float* x1r = x1 + (size_t)row0 * 512;
    const float* x2r = x2 + (size_t)row0 * 256;
    const float* x3r = x3 + (size_t)row0 * 128;

    for (int b = 0; b < 128; b++) {
        float a1[4][4], a2[4][2], a3[4];
        #pragma unroll
        for (int r = 0; r < 4; r++) {
            float4 v = *(const float4*)(x1r + (size_t)r * 512 + b * 4);
            a1[r][0] = v.x; a1[r][1] = v.y; a1[r][2] = v.z; a1[r][3] = v.w;
            float2 u = *(const float2*)(x2r + (size_t)r * 256 + b * 2);
            a2[r][0] = u.x; a2[r][1] = u.y;
            a3[r] = x3r[(size_t)r * 128 + b];
        }
        float t1[4], t2[4];

        #pragma unroll
        for (int r = 0; r < 4; r++) { t1[r] = a1[r][0]; t2[r] = a2[r][0]; }
        __syncwarp();
        do_step<0>(wsB, cm3, hb0, hb1, lane, offA, offB, t1, t2, a3, cst, hl);  // t%4==0

        #pragma unroll
        for (int r = 0; r < 4; r++) t1[r] = a1[r][1];
        __syncwarp();
        do_step<2>(wsB, cm1, hb1, hb0, lane, offA, offB, t1, t1, t1, cst, hl);  // t%4==1

        #pragma unroll
        for (int r = 0; r < 4; r++) { t1[r] = a1[r][2]; t2[r] = a2[r][1]; }
        __syncwarp();
        do_step<1>(wsB, cm2, hb0, hb1, lane, offA, offB, t1, t2, t2, cst, hl);  // t%4==2

        #pragma unroll
        for (int r = 0; r < 4; r++) t1[r] = a1[r][3];
        __syncwarp();
        do_step<2>(wsB, cm1, hb1, hb0, lane, offA, offB, t1, t1, t1, cst, hl);  // t%4==3
    }

    // out[row] = sigmoid(h . Wout + bOut): lane holds 2 units per row
    const float wo0 = Wout[u0], wo1 = Wout[u1];
    const float bo = bOut[0];
    #pragma unroll
    for (int r = 0; r < 4; r++) {
        float pw = hl[r][0] * wo0 + hl[r][1] * wo1;
        pw += __shfl_xor_sync(0xffffffffu, pw, 16);
        pw += __shfl_xor_sync(0xffffffffu, pw, 8);
        pw += __shfl_xor_sync(0xffffffffu, pw, 4);
        pw += __shfl_xor_sync(0xffffffffu, pw, 2);
        pw += __shfl_xor_sync(0xffffffffu, pw, 1);
        if (lane == 0) out[row0 + r] = sigp(pw + bo);
    }
}

extern "C" void kernel_launch(void* const* d_in, const int* in_sizes, int n_in,
                              void* d_out, int out_size) {
    const float* x1   = (const float*)d_in[0];
    const float* x2   = (const float*)d_in[1];
    const float* x3   = (const float*)d_in[2];
    const float* Wih3 = (const float*)d_in[3];
    const float* Whh3 = (const float*)d_in[4];
    const float* bih3 = (const float*)d_in[5];
    const float* bhh3 = (const float*)d_in[6];
    const float* Wih2 = (const float*)d_in[7];
    const float* Whh2 = (const float*)d_in[8];
    const float* bih2 = (const float*)d_in[9];
    const float* bhh2 = (const float*)d_in[10];
    const float* Wih1 = (const float*)d_in[11];
    const float* Whh1 = (const float*)d_in[12];
    const float* bih1 = (const float*)d_in[13];
    const float* bhh1 = (const float*)d_in[14];
    const float* Wout = (const float*)d_in[15];
    const float* bOut = (const float*)d_in[16];

    cudaFuncSetAttribute(mclstm_kernel, cudaFuncAttributeMaxDynamicSharedMemorySize, SMEM_BYTES);

    mclstm_kernel<<<NCTA, NTHR, SMEM_BYTES>>>(
        x1, x2, x3,
        Wih3, Whh3, bih3, bhh3,
        Wih2, Whh2, bih2, bhh2,
        Wih1, Whh1, bih1, bhh1,
        Wout, bOut, (float*)d_out);
}

// round 9
// speedup vs baseline: 1.5197x; 1.0021x over previous
#include <cuda_runtime.h>

// MultiCellLSTM: B=4096, T=512, H=64, gates 4H=256.
// R8: R4 architecture (4 rows/warp, warp-private recurrence, smem weights
// with conflict-free swizzle, dup'd double-buffered h, register-resident
// bias/input weights, tanh.approx activations) reshaped to 7 warps x 147
// CTAs so all 148 SMs carry work (was 128/148). Main loop is warp-private
// (no CTA sync), so the CTA shape is free; surplus warps exit after init.

typedef unsigned long long u64;

#define NTHR   224                  // 7 warps
#define NCTA   147                  // 147*7 = 1029 warps >= 1024 needed
#define NWARP  7
#define WS_U64 (3 * 64 * 128)       // 24576 u64 : recurrent weights (192KB)
#define HD_U64 (2 * 28 * 64)        // 3584  u64 : double-buffered dup'd h (28KB)
#define SMEM_BYTES ((WS_U64 + HD_U64) * 8)   // 225280

__device__ __forceinline__ float ex2f(float x) { float y; asm("ex2.approx.f32 %0, %1;" : "=f"(y) : "f"(x)); return y; }
__device__ __forceinline__ float rcpf(float x) { float y; asm("rcp.approx.f32 %0, %1;" : "=f"(y) : "f"(x)); return y; }
__device__ __forceinline__ float sigp(float x) { return rcpf(1.0f + ex2f(-1.4426950408889634f * x)); }  // final out only
__device__ __forceinline__ float tha(float x) { float y; asm("tanh.approx.f32 %0, %1;" : "=f"(y) : "f"(x)); return y; }
__device__ __forceinline__ float sga(float x) { return fmaf(0.5f, tha(0.5f * x), 0.5f); }

__device__ __forceinline__ u64 pk2(float a, float b) { u64 r; asm("mov.b64 %0, {%1, %2};" : "=l"(r) : "f"(a), "f"(b)); return r; }
__device__ __forceinline__ void up2(u64 v, float& a, float& b) { asm("mov.b64 {%0, %1}, %2;" : "=f"(a), "=f"(b) : "l"(v)); }
__device__ __forceinline__ u64 ffma2(u64 a, u64 b, u64 c) { u64 d; asm("fma.rn.f32x2 %0, %1, %2, %3;" : "=l"(d) : "l"(a), "l"(b), "l"(c)); return d; }

// Per-lane register-resident bias + input-weight columns.
// A = classes (i,f) for units (2l,2l+1); B = classes (g,o).
struct Cmb3 { ulonglong2 bA, bB, w1A, w1B, w2A, w2B, w3A, w3B; };
struct Cmb2 { ulonglong2 bA, bB, w1A, w1B, w2A, w2B; };
struct Cmb1 { ulonglong2 bA, bB, w1A, w1B; };

// One LSTM step for cell type TY (0: x1+x2+x3, 1: x1+x2, 2: x1 only).
// Lane owns units {2l,2l+1} x 4 rows. Weight k-row layout (1024B):
//   16B slot = l*32 + ((h ^ (l>>2))&1)*16; h=0 -> classes(i,f), h=1 -> (g,o).
// Half-swap makes each 8-lane LDS.128 phase tile all 32 banks once.
template<int TY, typename CMB>
__device__ __forceinline__ void do_step(
    const char* __restrict__ wsB, const CMB& cm,
    const char* __restrict__ hrd,   // read buffer (this warp's 4 rows x 512B)
    char* __restrict__ hwr,         // write buffer
    int lane, int offA, int offB,
    const float (&xv1)[4], const float (&xv2)[4], const float (&xv3)[4],
    float (&cst)[4][2], float (&hl)[4][2])
{
    const char* wcell = wsB + TY * 65536;   // 64 k-rows * 1024B

    u64 acc[4][4];  // [class i,f,g,o][row]

    #pragma unroll
    for (int r = 0; r < 4; r++) {
        u64 xd = pk2(xv1[r], xv1[r]);
        acc[0][r] = ffma2(cm.w1A.x, xd, cm.bA.x);
        acc[1][r] = ffma2(cm.w1A.y, xd, cm.bA.y);
        acc[2][r] = ffma2(cm.w1B.x, xd, cm.bB.x);
        acc[3][r] = ffma2(cm.w1B.y, xd, cm.bB.y);
    }
    if constexpr (TY <= 1) {
        #pragma unroll
        for (int r = 0; r < 4; r++) {
            u64 xd = pk2(xv2[r], xv2[r]);
            acc[0][r] = ffma2(cm.w2A.x, xd, acc[0][r]);
            acc[1][r] = ffma2(cm.w2A.y, xd, acc[1][r]);
            acc[2][r] = ffma2(cm.w2B.x, xd, acc[2][r]);
            acc[3][r] = ffma2(cm.w2B.y, xd, acc[3][r]);
        }
    }
    if constexpr (TY == 0) {
        #pragma unroll
        for (int r = 0; r < 4; r++) {
            u64 xd = pk2(xv3[r], xv3[r]);
            acc[0][r] = ffma2(cm.w3A.x, xd, acc[0][r]);
            acc[1][r] = ffma2(cm.w3A.y, xd, acc[1][r]);
            acc[2][r] = ffma2(cm.w3B.x, xd, acc[2][r]);
            acc[3][r] = ffma2(cm.w3B.y, xd, acc[3][r]);
        }
    }

    // recurrent: acc += Wh[:,k] * h[k]; k in pairs, weights shared by 4 rows
    #pragma unroll 8
    for (int m = 0; m < 32; m++) {
        const char* base = wcell + m * 2048;
        ulonglong2 w0A = *(const ulonglong2*)(base + offA);
        ulonglong2 w0B = *(const ulonglong2*)(base + offB);
        ulonglong2 w1A = *(const ulonglong2*)(base + 1024 + offA);
        ulonglong2 w1B = *(const ulonglong2*)(base + 1024 + offB);
        #pragma unroll
        for (int r = 0; r < 4; r++) {
            ulonglong2 hd = *(const ulonglong2*)(hrd + r * 512 + m * 16);  // (dup h_2m, dup h_2m+1)
            acc[0][r] = ffma2(w0A.x, hd.x, acc[0][r]);
            acc[1][r] = ffma2(w0A.y, hd.x, acc[1][r]);
            acc[2][r] = ffma2(w0B.x, hd.x, acc[2][r]);
            acc[3][r] = ffma2(w0B.y, hd.x, acc[3][r]);
            acc[0][r] = ffma2(w1A.x, hd.y, acc[0][r]);
            acc[1][r] = ffma2(w1A.y, hd.y, acc[1][r]);
            acc[2][r] = ffma2(w1B.x, hd.y, acc[2][r]);
            acc[3][r] = ffma2(w1B.y, hd.y, acc[3][r]);
        }
    }

    // elementwise LSTM cell (writes go to the other h buffer -> no sync here)
    #pragma unroll
    for (int r = 0; r < 4; r++) {
        float gi0, gi1, gf0, gf1, gg0, gg1, go0, go1;
        up2(acc[0][r], gi0, gi1);
        up2(acc[1][r], gf0, gf1);
        up2(acc[2][r], gg0, gg1);
        up2(acc[3][r], go0, go1);
        float c0 = fmaf(sga(gf0), cst[r][0], sga(gi0) * tha(gg0));
        float c1 = fmaf(sga(gf1), cst[r][1], sga(gi1) * tha(gg1));
        cst[r][0] = c0; cst[r][1] = c1;
        float h0 = sga(go0) * tha(c0);
        float h1 = sga(go1) * tha(c1);
        hl[r][0] = h0; hl[r][1] = h1;
        ulonglong2 st; st.x = pk2(h0, h0); st.y = pk2(h1, h1);
        *(ulonglong2*)(hwr + r * 512 + lane * 16) = st;   // dup'd store
    }
}

__global__ __launch_bounds__(NTHR, 1) void mclstm_kernel(
    const float* __restrict__ x1, const float* __restrict__ x2, const float* __restrict__ x3,
    const float* __restrict__ Wih3, const float* __restrict__ Whh3,
    const float* __restrict__ bih3, const float* __restrict__ bhh3,
    const float* __restrict__ Wih2, const float* __restrict__ Whh2,
    const float* __restrict__ bih2, const float* __restrict__ bhh2,
    const float* __restrict__ Wih1, const float* __restrict__ Whh1,
    const float* __restrict__ bih1, const float* __restrict__ bhh1,
    const float* __restrict__ Wout, const float* __restrict__ bOut,
    float* __restrict__ out)
{
    extern __shared__ u64 sm[];
    u64* ws   = sm;
    u64* hdup = ws + WS_U64;   // [par][28 rows][64 u64]

    const int tid = threadIdx.x;

    // ---- stage recurrent weights: ws[(ty*64+k)*128 + slot] ----
    // slot s -> lane l=s>>2, 16B half swz=(s>>1)&1, col=s&1;
    // logical half h = swz ^ ((l>>2)&1); class q = 2h+col; units (2l,2l+1).
    for (int idx = tid; idx < WS_U64; idx += NTHR) {
        int ty = idx >> 13, rem = idx & 8191, k = rem >> 7, s = rem & 127;
        int l = s >> 2, swz = (s >> 1) & 1, col = s & 1;
        int h = swz ^ ((l >> 2) & 1);
        int q = 2 * h + col;
        const float* W = (ty == 0) ? Whh3 : (ty == 1) ? Whh2 : Whh1;
        int g0 = (q * 64 + 2 * l) * 64 + k;
        ws[idx] = pk2(W[g0], W[g0 + 64]);
    }
    for (int idx = tid; idx < HD_U64; idx += NTHR) hdup[idx] = 0ull;

    const int lane = tid & 31, w = tid >> 5;
    const int gw   = blockIdx.x * NWARP + w;     // global warp id
    const int row0 = gw * 4;
    const int u0 = 2 * lane, u1 = u0 + 1;

    // ---- per-lane register cmb: bias(+bhh) and input-weight columns ----
    Cmb3 cm3; Cmb2 cm2; Cmb1 cm1;
    {
        // gate row = class*64 + unit; classes i=0,f=1,g=2,o=3
        #define LB(bi, bh, q) pk2(bi[(q)*64 + u0] + bh[(q)*64 + u0], bi[(q)*64 + u1] + bh[(q)*64 + u1])
        #define LW(wi, q, wic, cx) pk2(wi[((q)*64 + u0)*(wic) + (cx)], wi[((q)*64 + u1)*(wic) + (cx)])
        cm3.bA.x = LB(bih3, bhh3, 0); cm3.bA.y = LB(bih3, bhh3, 1);
        cm3.bB.x = LB(bih3, bhh3, 2); cm3.bB.y = LB(bih3, bhh3, 3);
        cm3.w1A.x = LW(Wih3, 0, 3, 0); cm3.w1A.y = LW(Wih3, 1, 3, 0);
        cm3.w1B.x = LW(Wih3, 2, 3, 0); cm3.w1B.y = LW(Wih3, 3, 3, 0);
        cm3.w2A.x = LW(Wih3, 0, 3, 1); cm3.w2A.y = LW(Wih3, 1, 3, 1);
        cm3.w2B.x = LW(Wih3, 2, 3, 1); cm3.w2B.y = LW(Wih3, 3, 3, 1);
        cm3.w3A.x = LW(Wih3, 0, 3, 2); cm3.w3A.y = LW(Wih3, 1, 3, 2);
        cm3.w3B.x = LW(Wih3, 2, 3, 2); cm3.w3B.y = LW(Wih3, 3, 3, 2);

        cm2.bA.x = LB(bih2, bhh2, 0); cm2.bA.y = LB(bih2, bhh2, 1);
        cm2.bB.x = LB(bih2, bhh2, 2); cm2.bB.y = LB(bih2, bhh2, 3);
        cm2.w1A.x = LW(Wih2, 0, 2, 0); cm2.w1A.y = LW(Wih2, 1, 2, 0);
        cm2.w1B.x = LW(Wih2, 2, 2, 0); cm2.w1B.y = LW(Wih2, 3, 2, 0);
        cm2.w2A.x = LW(Wih2, 0, 2, 1); cm2.w2A.y = LW(Wih2, 1, 2, 1);
        cm2.w2B.x = LW(Wih2, 2, 2, 1); cm2.w2B.y = LW(Wih2, 3, 2, 1);

        cm1.bA.x = LB(bih1, bhh1, 0); cm1.bA.y = LB(bih1, bhh1, 1);
        cm1.bB.x = LB(bih1, bhh1, 2); cm1.bB.y = LB(bih1, bhh1, 3);
        cm1.w1A.x = LW(Wih1, 0, 1, 0); cm1.w1A.y = LW(Wih1, 1, 1, 0);
        cm1.w1B.x = LW(Wih1, 2, 1, 0); cm1.w1B.y = LW(Wih1, 3, 1, 0);
        #undef LB
        #undef LW
    }
    __syncthreads();

    if (row0 >= 4096) return;   // surplus warps (tail CTA) exit after init

    const int s0   = ((lane >> 2) & 1) * 16;
    const int offA = lane * 32 + s0;        // classes (i,f)
    const int offB = lane * 32 + 16 - s0;   // classes (g,o)

    const char* wsB = (const char*)ws;
    char* hb0 = (char*)hdup + (size_t)w * 4 * 512;   // par 0, warp-private 2KB
    char* hb1 = hb0 + 28 * 512;                      // par 1

    float cst[4][2], hl[4][2];
    #pragma unroll
    for (int r = 0; r < 4; r++) { cst[r][0] = cst[r][1] = 0.f; hl[r][0] = hl[r][1] = 0.f; }

    const float* x1r = x1 + (size_t)row0 * 512;
    const float* x2r = x2 + (size_t)row0 * 256;
    const float* x3r = x3 + (size_t)row0 * 128;

    for (int b = 0; b < 128; b++) {
        float a1[4][4], a2[4][2], a3[4];
        #pragma unroll
        for (int r = 0; r < 4; r++) {
            float4 v = *(const float4*)(x1r + (size_t)r * 512 + b * 4);
            a1[r][0] = v.x; a1[r][1] = v.y; a1[r][2] = v.z; a1[r][3] = v.w;
            float2 u = *(const float2*)(x2r + (size_t)r * 256 + b * 2);
            a2[r][0] = u.x; a2[r][1] = u.y;
            a3[r] = x3r[(size_t)r * 128 + b];
        }
        float t1[4], t2[4];

        #pragma unroll
        for (int r = 0; r < 4; r++) { t1[r] = a1[r][0]; t2[r] = a2[r][0]; }
        __syncwarp();
        do_step<0>(wsB, cm3, hb0, hb1, lane, offA, offB, t1, t2, a3, cst, hl);  // t%4==0

        #pragma unroll
        for (int r = 0; r < 4; r++) t1[r] = a1[r][1];
        __syncwarp();
        do_step<2>(wsB, cm1, hb1, hb0, lane, offA, offB, t1, t1, t1, cst, hl);  // t%4==1

        #pragma unroll
        for (int r = 0; r < 4; r++) { t1[r] = a1[r][2]; t2[r] = a2[r][1]; }
        __syncwarp();
        do_step<1>(wsB, cm2, hb0, hb1, lane, offA, offB, t1, t2, t2, cst, hl);  // t%4==2

        #pragma unroll
        for (int r = 0; r < 4; r++) t1[r] = a1[r][3];
        __syncwarp();
        do_step<2>(wsB, cm1, hb1, hb0, lane, offA, offB, t1, t1, t1, cst, hl);  // t%4==3
    }

    // out[row] = sigmoid(h . Wout + bOut): lane holds 2 units per row
    const float wo0 = Wout[u0], wo1 = Wout[u1];
    const float bo = bOut[0];
    #pragma unroll
    for (int r = 0; r < 4; r++) {
        float pw = hl[r][0] * wo0 + hl[r][1] * wo1;
        pw += __shfl_xor_sync(0xffffffffu, pw, 16);
        pw += __shfl_xor_sync(0xffffffffu, pw, 8);
        pw += __shfl_xor_sync(0xffffffffu, pw, 4);
        pw += __shfl_xor_sync(0xffffffffu, pw, 2);
        pw += __shfl_xor_sync(0xffffffffu, pw, 1);
        if (lane == 0) out[row0 + r] = sigp(pw + bo);
    }
}

extern "C" void kernel_launch(void* const* d_in, const int* in_sizes, int n_in,
                              void* d_out, int out_size) {
    const float* x1   = (const float*)d_in[0];
    const float* x2   = (const float*)d_in[1];
    const float* x3   = (const float*)d_in[2];
    const float* Wih3 = (const float*)d_in[3];
    const float* Whh3 = (const float*)d_in[4];
    const float* bih3 = (const float*)d_in[5];
    const float* bhh3 = (const float*)d_in[6];
    const float* Wih2 = (const float*)d_in[7];
    const float* Whh2 = (const float*)d_in[8];
    const float* bih2 = (const float*)d_in[9];
    const float* bhh2 = (const float*)d_in[10];
    const float* Wih1 = (const float*)d_in[11];
    const float* Whh1 = (const float*)d_in[12];
    const float* bih1 = (const float*)d_in[13];
    const float* bhh1 = (const float*)d_in[14];
    const float* Wout = (const float*)d_in[15];
    const float* bOut = (const float*)d_in[16];

    cudaFuncSetAttribute(mclstm_kernel, cudaFuncAttributeMaxDynamicSharedMemorySize, SMEM_BYTES);

    mclstm_kernel<<<NCTA, NTHR, SMEM_BYTES>>>(
        x1, x2, x3,
        Wih3, Whh3, bih3, bhh3,
        Wih2, Whh2, bih2, bhh2,
        Wih1, Whh1, bih1, bhh1,
        Wout, bOut, (float*)d_out);
}

// round 10
// speedup vs baseline: 1.5218x; 1.0014x over previous
#include <cuda_runtime.h>

// MultiCellLSTM: B=4096, T=512, H=64, gates 4H=256.
// R10: R8 (7 warps x 147 CTAs, 4 rows/warp, smem weights w/ conflict-free
// swizzle, dup'd double-buffered h, register cmb, tanh.approx) with the
// per-step __syncwarp fences REMOVED. The warp is fully converged and h is
// double-buffered: cross-step ordering is enforced by address aliasing
// (same-buffer accesses keep program order), while independent next-step
// weight loads may now be scheduled into the elementwise MUFU tail.
// h pointers lose __restrict__ so nvcc sees the aliasing too.

typedef unsigned long long u64;

#define NTHR   224                  // 7 warps
#define NCTA   147                  // 147*7 = 1029 warps >= 1024 needed
#define NWARP  7
#define WS_U64 (3 * 64 * 128)       // 24576 u64 : recurrent weights (192KB)
#define HD_U64 (2 * 28 * 64)        // 3584  u64 : double-buffered dup'd h (28KB)
#define SMEM_BYTES ((WS_U64 + HD_U64) * 8)   // 225280

__device__ __forceinline__ float ex2f(float x) { float y; asm("ex2.approx.f32 %0, %1;" : "=f"(y) : "f"(x)); return y; }
__device__ __forceinline__ float rcpf(float x) { float y; asm("rcp.approx.f32 %0, %1;" : "=f"(y) : "f"(x)); return y; }
__device__ __forceinline__ float sigp(float x) { return rcpf(1.0f + ex2f(-1.4426950408889634f * x)); }  // final out only
__device__ __forceinline__ float tha(float x) { float y; asm("tanh.approx.f32 %0, %1;" : "=f"(y) : "f"(x)); return y; }
__device__ __forceinline__ float sga(float x) { return fmaf(0.5f, tha(0.5f * x), 0.5f); }

__device__ __forceinline__ u64 pk2(float a, float b) { u64 r; asm("mov.b64 %0, {%1, %2};" : "=l"(r) : "f"(a), "f"(b)); return r; }
__device__ __forceinline__ void up2(u64 v, float& a, float& b) { asm("mov.b64 {%0, %1}, %2;" : "=f"(a), "=f"(b) : "l"(v)); }
__device__ __forceinline__ u64 ffma2(u64 a, u64 b, u64 c) { u64 d; asm("fma.rn.f32x2 %0, %1, %2, %3;" : "=l"(d) : "l"(a), "l"(b), "l"(c)); return d; }

// Per-lane register-resident bias + input-weight columns.
// A = classes (i,f) for units (2l,2l+1); B = classes (g,o).
struct Cmb3 { ulonglong2 bA, bB, w1A, w1B, w2A, w2B, w3A, w3B; };
struct Cmb2 { ulonglong2 bA, bB, w1A, w1B, w2A, w2B; };
struct Cmb1 { ulonglong2 bA, bB, w1A, w1B; };

// One LSTM step for cell type TY (0: x1+x2+x3, 1: x1+x2, 2: x1 only).
// Lane owns units {2l,2l+1} x 4 rows. Weight k-row layout (1024B):
//   16B slot = l*32 + ((h ^ (l>>2))&1)*16; h=0 -> classes(i,f), h=1 -> (g,o).
// Half-swap makes each 8-lane LDS.128 phase tile all 32 banks once.
// NOTE: hrd/hwr intentionally NOT __restrict__ — aliasing with other steps'
// buffers is what keeps cross-step ordering correct without barriers.
template<int TY, typename CMB>
__device__ __forceinline__ void do_step(
    const char* __restrict__ wsB, const CMB& cm,
    const char* hrd,   // read buffer (this warp's 4 rows x 512B)
    char* hwr,         // write buffer
    int lane, int offA, int offB,
    const float (&xv1)[4], const float (&xv2)[4], const float (&xv3)[4],
    float (&cst)[4][2], float (&hl)[4][2])
{
    const char* wcell = wsB + TY * 65536;   // 64 k-rows * 1024B

    u64 acc[4][4];  // [class i,f,g,o][row]

    #pragma unroll
    for (int r = 0; r < 4; r++) {
        u64 xd = pk2(xv1[r], xv1[r]);
        acc[0][r] = ffma2(cm.w1A.x, xd, cm.bA.x);
        acc[1][r] = ffma2(cm.w1A.y, xd, cm.bA.y);
        acc[2][r] = ffma2(cm.w1B.x, xd, cm.bB.x);
        acc[3][r] = ffma2(cm.w1B.y, xd, cm.bB.y);
    }
    if constexpr (TY <= 1) {
        #pragma unroll
        for (int r = 0; r < 4; r++) {
            u64 xd = pk2(xv2[r], xv2[r]);
            acc[0][r] = ffma2(cm.w2A.x, xd, acc[0][r]);
            acc[1][r] = ffma2(cm.w2A.y, xd, acc[1][r]);
            acc[2][r] = ffma2(cm.w2B.x, xd, acc[2][r]);
            acc[3][r] = ffma2(cm.w2B.y, xd, acc[3][r]);
        }
    }
    if constexpr (TY == 0) {
        #pragma unroll
        for (int r = 0; r < 4; r++) {
            u64 xd = pk2(xv3[r], xv3[r]);
            acc[0][r] = ffma2(cm.w3A.x, xd, acc[0][r]);
            acc[1][r] = ffma2(cm.w3A.y, xd, acc[1][r]);
            acc[2][r] = ffma2(cm.w3B.x, xd, acc[2][r]);
            acc[3][r] = ffma2(cm.w3B.y, xd, acc[3][r]);
        }
    }

    // recurrent: acc += Wh[:,k] * h[k]; k in pairs, weights shared by 4 rows
    #pragma unroll 8
    for (int m = 0; m < 32; m++) {
        const char* base = wcell + m * 2048;
        ulonglong2 w0A = *(const ulonglong2*)(base + offA);
        ulonglong2 w0B = *(const ulonglong2*)(base + offB);
        ulonglong2 w1A = *(const ulonglong2*)(base + 1024 + offA);
        ulonglong2 w1B = *(const ulonglong2*)(base + 1024 + offB);
        #pragma unroll
        for (int r = 0; r < 4; r++) {
            ulonglong2 hd = *(const ulonglong2*)(hrd + r * 512 + m * 16);  // (dup h_2m, dup h_2m+1)
            acc[0][r] = ffma2(w0A.x, hd.x, acc[0][r]);
            acc[1][r] = ffma2(w0A.y, hd.x, acc[1][r]);
            acc[2][r] = ffma2(w0B.x, hd.x, acc[2][r]);
            acc[3][r] = ffma2(w0B.y, hd.x, acc[3][r]);
            acc[0][r] = ffma2(w1A.x, hd.y, acc[0][r]);
            acc[1][r] = ffma2(w1A.y, hd.y, acc[1][r]);
            acc[2][r] = ffma2(w1B.x, hd.y, acc[2][r]);
            acc[3][r] = ffma2(w1B.y, hd.y, acc[3][r]);
        }
    }

    // elementwise LSTM cell (writes go to the other h buffer)
    #pragma unroll
    for (int r = 0; r < 4; r++) {
        float gi0, gi1, gf0, gf1, gg0, gg1, go0, go1;
        up2(acc[0][r], gi0, gi1);
        up2(acc[1][r], gf0, gf1);
        up2(acc[2][r], gg0, gg1);
        up2(acc[3][r], go0, go1);
        float c0 = fmaf(sga(gf0), cst[r][0], sga(gi0) * tha(gg0));
        float c1 = fmaf(sga(gf1), cst[r][1], sga(gi1) * tha(gg1));
        cst[r][0] = c0; cst[r][1] = c1;
        float h0 = sga(go0) * tha(c0);
        float h1 = sga(go1) * tha(c1);
        hl[r][0] = h0; hl[r][1] = h1;
        ulonglong2 st; st.x = pk2(h0, h0); st.y = pk2(h1, h1);
        *(ulonglong2*)(hwr + r * 512 + lane * 16) = st;   // dup'd store
    }
}

__global__ __launch_bounds__(NTHR, 1) void mclstm_kernel(
    const float* __restrict__ x1, const float* __restrict__ x2, const float* __restrict__ x3,
    const float* __restrict__ Wih3, const float* __restrict__ Whh3,
    const float* __restrict__ bih3, const float* __restrict__ bhh3,
    const float* __restrict__ Wih2, const float* __restrict__ Whh2,
    const float* __restrict__ bih2, const float* __restrict__ bhh2,
    const float* __restrict__ Wih1, const float* __restrict__ Whh1,
    const float* __restrict__ bih1, const float* __restrict__ bhh1,
    const float* __restrict__ Wout, const float* __restrict__ bOut,
    float* __restrict__ out)
{
    extern __shared__ u64 sm[];
    u64* ws   = sm;
    u64* hdup = ws + WS_U64;   // [par][28 rows][64 u64]

    const int tid = threadIdx.x;

    // ---- stage recurrent weights: ws[(ty*64+k)*128 + slot] ----
    // slot s -> lane l=s>>2, 16B half swz=(s>>1)&1, col=s&1;
    // logical half h = swz ^ ((l>>2)&1); class q = 2h+col; units (2l,2l+1).
    for (int idx = tid; idx < WS_U64; idx += NTHR) {
        int ty = idx >> 13, rem = idx & 8191, k = rem >> 7, s = rem & 127;
        int l = s >> 2, swz = (s >> 1) & 1, col = s & 1;
        int h = swz ^ ((l >> 2) & 1);
        int q = 2 * h + col;
        const float* W = (ty == 0) ? Whh3 : (ty == 1) ? Whh2 : Whh1;
        int g0 = (q * 64 + 2 * l) * 64 + k;
        ws[idx] = pk2(W[g0], W[g0 + 64]);
    }
    for (int idx = tid; idx < HD_U64; idx += NTHR) hdup[idx] = 0ull;

    const int lane = tid & 31, w = tid >> 5;
    const int gw   = blockIdx.x * NWARP + w;     // global warp id
    const int row0 = gw * 4;
    const int u0 = 2 * lane, u1 = u0 + 1;

    // ---- per-lane register cmb: bias(+bhh) and input-weight columns ----
    Cmb3 cm3; Cmb2 cm2; Cmb1 cm1;
    {
        // gate row = class*64 + unit; classes i=0,f=1,g=2,o=3
        #define LB(bi, bh, q) pk2(bi[(q)*64 + u0] + bh[(q)*64 + u0], bi[(q)*64 + u1] + bh[(q)*64 + u1])
        #define LW(wi, q, wic, cx) pk2(wi[((q)*64 + u0)*(wic) + (cx)], wi[((q)*64 + u1)*(wic) + (cx)])
        cm3.bA.x = LB(bih3, bhh3, 0); cm3.bA.y = LB(bih3, bhh3, 1);
        cm3.bB.x = LB(bih3, bhh3, 2); cm3.bB.y = LB(bih3, bhh3, 3);
        cm3.w1A.x = LW(Wih3, 0, 3, 0); cm3.w1A.y = LW(Wih3, 1, 3, 0);
        cm3.w1B.x = LW(Wih3, 2, 3, 0); cm3.w1B.y = LW(Wih3, 3, 3, 0);
        cm3.w2A.x = LW(Wih3, 0, 3, 1); cm3.w2A.y = LW(Wih3, 1, 3, 1);
        cm3.w2B.x = LW(Wih3, 2, 3, 1); cm3.w2B.y = LW(Wih3, 3, 3, 1);
        cm3.w3A.x = LW(Wih3, 0, 3, 2); cm3.w3A.y = LW(Wih3, 1, 3, 2);
        cm3.w3B.x = LW(Wih3, 2, 3, 2); cm3.w3B.y = LW(Wih3, 3, 3, 2);

        cm2.bA.x = LB(bih2, bhh2, 0); cm2.bA.y = LB(bih2, bhh2, 1);
        cm2.bB.x = LB(bih2, bhh2, 2); cm2.bB.y = LB(bih2, bhh2, 3);
        cm2.w1A.x = LW(Wih2, 0, 2, 0); cm2.w1A.y = LW(Wih2, 1, 2, 0);
        cm2.w1B.x = LW(Wih2, 2, 2, 0); cm2.w1B.y = LW(Wih2, 3, 2, 0);
        cm2.w2A.x = LW(Wih2, 0, 2, 1); cm2.w2A.y = LW(Wih2, 1, 2, 1);
        cm2.w2B.x = LW(Wih2, 2, 2, 1); cm2.w2B.y = LW(Wih2, 3, 2, 1);

        cm1.bA.x = LB(bih1, bhh1, 0); cm1.bA.y = LB(bih1, bhh1, 1);
        cm1.bB.x = LB(bih1, bhh1, 2); cm1.bB.y = LB(bih1, bhh1, 3);
        cm1.w1A.x = LW(Wih1, 0, 1, 0); cm1.w1A.y = LW(Wih1, 1, 1, 0);
        cm1.w1B.x = LW(Wih1, 2, 1, 0); cm1.w1B.y = LW(Wih1, 3, 1, 0);
        #undef LB
        #undef LW
    }
    __syncthreads();

    if (row0 >= 4096) return;   // surplus warps (tail CTA) exit after init

    const int s0   = ((lane >> 2) & 1) * 16;
    const int offA = lane * 32 + s0;        // classes (i,f)
    const int offB = lane * 32 + 16 - s0;   // classes (g,o)

    const char* wsB = (const char*)ws;
    char* hb0 = (char*)hdup + (size_t)w * 4 * 512;   // par 0, warp-private 2KB
    char* hb1 = hb0 + 28 * 512;                      // par 1

    float cst[4][2], hl[4][2];
    #pragma unroll
    for (int r = 0; r < 4; r++) { cst[r][0] = cst[r][1] = 0.f; hl[r][0] = hl[r][1] = 0.f; }

    const float* x1r = x1 + (size_t)row0 * 512;
    const float* x2r = x2 + (size_t)row0 * 256;
    const float* x3r = x3 + (size_t)row0 * 128;

    for (int b = 0; b < 128; b++) {
        float a1[4][4], a2[4][2], a3[4];
        #pragma unroll
        for (int r = 0; r < 4; r++) {
            float4 v = *(const float4*)(x1r + (size_t)r * 512 + b * 4);
            a1[r][0] = v.x; a1[r][1] = v.y; a1[r][2] = v.z; a1[r][3] = v.w;
            float2 u = *(const float2*)(x2r + (size_t)r * 256 + b * 2);
            a2[r][0] = u.x; a2[r][1] = u.y;
            a3[r] = x3r[(size_t)r * 128 + b];
        }
        float t1[4], t2[4];

        #pragma unroll
        for (int r = 0; r < 4; r++) { t1[r] = a1[r][0]; t2[r] = a2[r][0]; }
        do_step<0>(wsB, cm3, hb0, hb1, lane, offA, offB, t1, t2, a3, cst, hl);  // t%4==0

        #pragma unroll
        for (int r = 0; r < 4; r++) t1[r] = a1[r][1];
        do_step<2>(wsB, cm1, hb1, hb0, lane, offA, offB, t1, t1, t1, cst, hl);  // t%4==1

        #pragma unroll
        for (int r = 0; r < 4; r++) { t1[r] = a1[r][2]; t2[r] = a2[r][1]; }
        do_step<1>(wsB, cm2, hb0, hb1, lane, offA, offB, t1, t2, t2, cst, hl);  // t%4==2

        #pragma unroll
        for (int r = 0; r < 4; r++) t1[r] = a1[r][3];
        do_step<2>(wsB, cm1, hb1, hb0, lane, offA, offB, t1, t1, t1, cst, hl);  // t%4==3
    }

    // out[row] = sigmoid(h . Wout + bOut): lane holds 2 units per row
    const float wo0 = Wout[u0], wo1 = Wout[u1];
    const float bo = bOut[0];
    #pragma unroll
    for (int r = 0; r < 4; r++) {
        float pw = hl[r][0] * wo0 + hl[r][1] * wo1;
        pw += __shfl_xor_sync(0xffffffffu, pw, 16);
        pw += __shfl_xor_sync(0xffffffffu, pw, 8);
        pw += __shfl_xor_sync(0xffffffffu, pw, 4);
        pw += __shfl_xor_sync(0xffffffffu, pw, 2);
        pw += __shfl_xor_sync(0xffffffffu, pw, 1);
        if (lane == 0) out[row0 + r] = sigp(pw + bo);
    }
}

extern "C" void kernel_launch(void* const* d_in, const int* in_sizes, int n_in,
                              void* d_out, int out_size) {
    const float* x1   = (const float*)d_in[0];
    const float* x2   = (const float*)d_in[1];
    const float* x3   = (const float*)d_in[2];
    const float* Wih3 = (const float*)d_in[3];
    const float* Whh3 = (const float*)d_in[4];
    const float* bih3 = (const float*)d_in[5];
    const float* bhh3 = (const float*)d_in[6];
    const float* Wih2 = (const float*)d_in[7];
    const float* Whh2 = (const float*)d_in[8];
    const float* bih2 = (const float*)d_in[9];
    const float* bhh2 = (const float*)d_in[10];
    const float* Wih1 = (const float*)d_in[11];
    const float* Whh1 = (const float*)d_in[12];
    const float* bih1 = (const float*)d_in[13];
    const float* bhh1 = (const float*)d_in[14];
    const float* Wout = (const float*)d_in[15];
    const float* bOut = (const float*)d_in[16];

    cudaFuncSetAttribute(mclstm_kernel, cudaFuncAttributeMaxDynamicSharedMemorySize, SMEM_BYTES);

    mclstm_kernel<<<NCTA, NTHR, SMEM_BYTES>>>(
        x1, x2, x3,
        Wih3, Whh3, bih3, bhh3,
        Wih2, Whh2, bih2, bhh2,
        Wih1, Whh1, bih1, bhh1,
        Wout, bOut, (float*)d_out);
}